// round 3
// baseline (speedup 1.0000x reference)
#include <cuda_runtime.h>

#define BB 16
#define NN 2048
#define KK 10
#define FULLM 0xffffffffu
#define QPW 4                 // queries per warp

__device__ int   g_idx[BB * NN * KK];
__device__ float g_loss[BB * NN];

// ---------------------------------------------------------------------------
// Kernel 1: warp-per-4-queries masked KNN.
// Four sorted top-10 lists per warp, each striped over lanes 0..9 in its own
// u64 register. Key = (float_bits(d2 + 1e-7) << 32) | idx  (exact stable
// top_k semantics, identical FP expressions to the passing round-2 kernel).
// ---------------------------------------------------------------------------
__global__ void __launch_bounds__(512) knn_kernel(const float* __restrict__ src) {
    __shared__ float4 sp[NN];
    const int b     = blockIdx.x >> 5;   // 32 blocks per batch (64 queries each)
    const int chunk = blockIdx.x & 31;
    const float* base = src + (size_t)b * 3 * NN;

    for (int i = threadIdx.x; i < NN; i += 512) {
        float x = base[i];
        float y = base[NN + i];
        float z = base[2 * NN + i];
        sp[i] = make_float4(x, y, z, x * x + y * y + z * z);
    }
    __syncthreads();

    const int warp  = threadIdx.x >> 5;
    const int lane  = threadIdx.x & 31;
    const int qbase = chunk * (16 * QPW) + warp * QPW;

    float Qx[QPW], Qy[QPW], Qz[QPW], Qw[QPW];
#pragma unroll
    for (int qi = 0; qi < QPW; qi++) {
        float4 Q = sp[qbase + qi];
        Qx[qi] = Q.x; Qy[qi] = Q.y; Qz[qi] = Q.z; Qw[qi] = Q.w;
    }

    unsigned long long key[QPW];
    unsigned tau[QPW];
#pragma unroll
    for (int qi = 0; qi < QPW; qi++) { key[qi] = ~0ULL; tau[qi] = 0xFFFFFFFFu; }

    for (int batch = 0; batch < NN / 32; batch++) {
        float4 p = sp[batch * 32 + lane];
#pragma unroll
        for (int qi = 0; qi < QPW; qi++) {
            float dot = Qx[qi] * p.x + Qy[qi] * p.y + Qz[qi] * p.z;
            float d2f = (Qw[qi] + p.w - 2.0f * dot) + 1e-7f;   // ref: d2 + 1e-7
            unsigned du = __float_as_uint(d2f);
            // ref mask: excluded iff d2f < 0.1
            bool pred = (d2f >= 0.1f) && (du <= tau[qi]);
            unsigned m = __ballot_sync(FULLM, pred);
            while (m) {
                int s = __ffs(m) - 1;
                m &= m - 1;
                unsigned kb = __shfl_sync(FULLM, du, s);
                unsigned long long k =
                    ((unsigned long long)kb << 32) | (unsigned)(batch * 32 + s);
                unsigned long long up = __shfl_up_sync(FULLM, key[qi], 1);
                bool c = (k < key[qi]);
                unsigned long long ins = (lane == 0 || up <= k) ? k : up;
                key[qi] = c ? ins : key[qi];
            }
            tau[qi] = __shfl_sync(FULLM, (unsigned)(key[qi] >> 32), 9);
        }
    }

#pragma unroll
    for (int qi = 0; qi < QPW; qi++) {
        const int q = qbase + qi;
        int* op = g_idx + ((size_t)(b * NN) + q) * KK;

        unsigned vm = __ballot_sync(FULLM, key[qi] != ~0ULL) & 0x3FFu;
        int cnt = __popc(vm);
        if (lane < cnt) op[lane] = (int)(unsigned)key[qi];

        // Rare fallback: fewer than 10 valid neighbors -> top_k fills with the
        // smallest masked indices (all tied at -inf).
        if (cnt < KK && lane == 0) {
            int slot = cnt;
            for (int i = 0; i < NN && slot < KK; i++) {
                float4 p = sp[i];
                float dot = Qx[qi] * p.x + Qy[qi] * p.y + Qz[qi] * p.z;
                float d2f = (Qw[qi] + p.w - 2.0f * dot) + 1e-7f;
                if (!(d2f >= 0.1f)) op[slot++] = i;
            }
        }
    }
}

// ---------------------------------------------------------------------------
// Kernel 2: 45 triangle pair losses per point, mean of sqrt of 10 smallest
// ---------------------------------------------------------------------------
__device__ __forceinline__ void sort3(float& a, float& b, float& c) {
    float t0 = fminf(a, b), t1 = fmaxf(a, b);
    float hi = fmaxf(t1, c);
    float mm = fminf(t1, c);
    float lo = fminf(t0, mm);
    float mi = fmaxf(t0, mm);
    a = lo; b = mi; c = hi;
}

#define K2_BLK 256

__global__ void __launch_bounds__(K2_BLK) loss_kernel(const float* __restrict__ src,
                                                      const float* __restrict__ tgt) {
    __shared__ float ssx[NN], ssy[NN], ssz[NN];
    __shared__ float stx[NN], sty[NN], stz[NN];
    const int blocksPerB = NN / K2_BLK;
    const int b     = blockIdx.x / blocksPerB;
    const int chunk = blockIdx.x % blocksPerB;
    const float* sb = src + (size_t)b * 3 * NN;
    const float* tb = tgt + (size_t)b * 3 * NN;

    for (int i = threadIdx.x; i < NN; i += K2_BLK) {
        ssx[i] = sb[i]; ssy[i] = sb[NN + i]; ssz[i] = sb[2 * NN + i];
        stx[i] = tb[i]; sty[i] = tb[NN + i]; stz[i] = tb[2 * NN + i];
    }
    __syncthreads();

    const int n = chunk * K2_BLK + threadIdx.x;
    const int* nb = g_idx + ((size_t)(b * NN) + n) * KK;

    float px[KK + 1], py[KK + 1], pz[KK + 1];
    float tx[KK + 1], ty[KK + 1], tz[KK + 1];
    px[0] = ssx[n]; py[0] = ssy[n]; pz[0] = ssz[n];
    tx[0] = stx[n]; ty[0] = sty[n]; tz[0] = stz[n];
#pragma unroll
    for (int j = 0; j < KK; j++) {
        int m = nb[j];
        px[j + 1] = ssx[m]; py[j + 1] = ssy[m]; pz[j + 1] = ssz[m];
        tx[j + 1] = stx[m]; ty[j + 1] = sty[m]; tz[j + 1] = stz[m];
    }

    const float INF = __int_as_float(0x7f800000);
    float ls[KK];
#pragma unroll
    for (int j = 0; j < KK; j++) ls[j] = INF;
    float worst = INF;

#pragma unroll
    for (int a = 0; a < KK - 1; a++) {
#pragma unroll
        for (int c = a + 1; c < KK; c++) {
            const int ia = a + 1, ic = c + 1;
            float dx, dy, dz;
            dx = px[0] - px[ia]; dy = py[0] - py[ia]; dz = pz[0] - pz[ia];
            float s01 = dx * dx + dy * dy + dz * dz;
            dx = px[ia] - px[ic]; dy = py[ia] - py[ic]; dz = pz[ia] - pz[ic];
            float s12 = dx * dx + dy * dy + dz * dz;
            dx = px[0] - px[ic]; dy = py[0] - py[ic]; dz = pz[0] - pz[ic];
            float s02 = dx * dx + dy * dy + dz * dz;
            sort3(s01, s12, s02);
            dx = tx[0] - tx[ia]; dy = ty[0] - ty[ia]; dz = tz[0] - tz[ia];
            float t01 = dx * dx + dy * dy + dz * dz;
            dx = tx[ia] - tx[ic]; dy = ty[ia] - ty[ic]; dz = tz[ia] - tz[ic];
            float t12 = dx * dx + dy * dy + dz * dz;
            dx = tx[0] - tx[ic]; dy = ty[0] - ty[ic]; dz = tz[0] - tz[ic];
            float t02 = dx * dx + dy * dy + dz * dz;
            sort3(t01, t12, t02);
            t01 += 1e-6f; t12 += 1e-6f; t02 += 1e-6f;

            float n0 = s01 - t01, n1 = s12 - t12, n2 = s02 - t02;
            float num = n0 * n0 + n1 * n1 + n2 * n2;
            float p0 = s01 + t01, p1 = s12 + t12, p2 = s02 + t02;
            float den = p0 * p0 + p1 * p1 + p2 * p2;
            float L = num / den;

            if (L < worst) {
                float cd = L;
#pragma unroll
                for (int j = 0; j < KK; j++) {
                    if (cd < ls[j]) { float t = ls[j]; ls[j] = cd; cd = t; }
                }
                worst = ls[KK - 1];
            }
        }
    }

    float acc = 0.0f;
#pragma unroll
    for (int j = 0; j < KK; j++) acc += sqrtf(ls[j] + 1e-6f);
    g_loss[b * NN + n] = acc * 0.1f;
}

// ---------------------------------------------------------------------------
// Kernel 3: per-batch min, sigmoid weight, threshold
// ---------------------------------------------------------------------------
__global__ void __launch_bounds__(256) weight_kernel(float* __restrict__ out) {
    const int b   = blockIdx.x;
    const int tid = threadIdx.x;
    const float* lp = g_loss + b * NN;

    float m = __int_as_float(0x7f800000);
    for (int i = tid; i < NN; i += 256) m = fminf(m, lp[i]);
#pragma unroll
    for (int o = 16; o; o >>= 1) m = fminf(m, __shfl_xor_sync(0xffffffffu, m, o));

    __shared__ float wmin[8];
    if ((tid & 31) == 0) wmin[tid >> 5] = m;
    __syncthreads();
    if (tid < 8) {
        float v = wmin[tid];
#pragma unroll
        for (int o = 4; o; o >>= 1) v = fminf(v, __shfl_xor_sync(0x000000ffu, v, o));
        if (tid == 0) wmin[0] = v;
    }
    __syncthreads();
    const float bmin = wmin[0];

    for (int i = tid; i < NN; i += 256) {
        float x = lp[i] - bmin;
        float w = 2.0f / (1.0f + expf(30.0f * x));
        out[b * NN + i] = (w > 0.6f) ? 1.0f : 0.0f;
    }
}

// ---------------------------------------------------------------------------
extern "C" void kernel_launch(void* const* d_in, const int* in_sizes, int n_in,
                              void* d_out, int out_size) {
    const float* src = (const float*)d_in[0];
    const float* tgt = (const float*)d_in[1];
    float* out = (float*)d_out;

    knn_kernel <<<BB * (NN / (16 * QPW)), 512>>>(src);
    loss_kernel<<<BB * (NN / K2_BLK), K2_BLK>>>(src, tgt);
    weight_kernel<<<BB, 256>>>(out);
}